// round 3
// baseline (speedup 1.0000x reference)
#include <cuda_runtime.h>
#include <cstdint>

#define TPB     160          // 128 compute threads + 32 producer (1 warp)
#define NCOMP   128
#define TILE    128
#define NSTAGE  3            // input ring depth
#define NBLK_MAX 592         // 148 SMs * 4 blocks (53.3 KB smem each)

#define IN_FLOATS  (TILE * 26)
#define OUT_FLOATS (TILE * 13)
#define IN_BYTES   (IN_FLOATS * 4)

__device__ __forceinline__ uint32_t s2u(const void* p) {
    return (uint32_t)__cvta_generic_to_shared(p);
}
__device__ __forceinline__ void bulk_g2s(uint32_t dst, const void* src, int bytes, uint32_t mb) {
    asm volatile(
        "cp.async.bulk.shared::cta.global.mbarrier::complete_tx::bytes [%0], [%1], %2, [%3];"
        :: "r"(dst), "l"(src), "r"(bytes), "r"(mb) : "memory");
}
__device__ __forceinline__ void bulk_s2g(void* dst, uint32_t src, int bytes) {
    asm volatile(
        "cp.async.bulk.global.shared::cta.bulk_group [%0], [%1], %2;"
        :: "l"(dst), "r"(src), "r"(bytes) : "memory");
}
__device__ __forceinline__ void mbar_init(uint32_t mb, int cnt) {
    asm volatile("mbarrier.init.shared.b64 [%0], %1;" :: "r"(mb), "r"(cnt) : "memory");
}
__device__ __forceinline__ void mbar_expect_tx(uint32_t mb, int bytes) {
    asm volatile("mbarrier.arrive.expect_tx.shared.b64 _, [%0], %1;"
                 :: "r"(mb), "r"(bytes) : "memory");
}
__device__ __forceinline__ void mbar_arrive(uint32_t mb) {
    asm volatile("mbarrier.arrive.shared.b64 _, [%0];" :: "r"(mb) : "memory");
}
__device__ __forceinline__ void mbar_wait(uint32_t mb, int parity) {
    asm volatile(
        "{\n\t.reg .pred P;\n\t"
        "WL_%=:\n\t"
        "mbarrier.try_wait.parity.shared.b64 P, [%0], %1, 0x989680;\n\t"
        "@P bra.uni WD_%=;\n\t"
        "bra.uni WL_%=;\n\t"
        "WD_%=:\n\t}"
        :: "r"(mb), "r"(parity) : "memory");
}

__device__ __forceinline__ void tp_compute(
    float a, float b, const float* u, const float* v,
    const float* A, const float* B,
    float& z0, float* z1, float* z2)
{
    z0 = a * b;
    #pragma unroll
    for (int i = 0; i < 3; i++) z0 = fmaf(u[i], v[i], z0);
    #pragma unroll
    for (int i = 0; i < 9; i++) z0 = fmaf(A[i], B[i], z0);

    #pragma unroll
    for (int i = 0; i < 3; i++) {
        float s = fmaf(a, v[i], b * u[i]);
        #pragma unroll
        for (int d = 0; d < 3; d++) {
            s = fmaf(u[d], B[d * 3 + i], s);       // u . B
            s = fmaf(A[i * 3 + d], v[d], s);       // A . v
        }
        z1[i] = s;
    }
    #pragma unroll
    for (int i = 0; i < 3; i++)
        #pragma unroll
        for (int j = 0; j < 3; j++) {
            float s = fmaf(a, B[i * 3 + j], b * A[i * 3 + j]);
            s = fmaf(u[i], v[j], s);
            #pragma unroll
            for (int k = 0; k < 3; k++)
                s = fmaf(A[i * 3 + k], B[k * 3 + j], s);   // A @ B
            z2[i * 3 + j] = s;
        }
}

__global__ __launch_bounds__(TPB) void tp_ws(
    const float* __restrict__ x0, const float* __restrict__ y0,
    const float* __restrict__ x1, const float* __restrict__ y1,
    const float* __restrict__ x2, const float* __restrict__ y2,
    float* __restrict__ out, long long NC)
{
    __shared__ __align__(16) float sIn[NSTAGE][IN_FLOATS];
    __shared__ __align__(16) float sOut[2][OUT_FLOATS];
    __shared__ __align__(8) unsigned long long mb_full[NSTAGE];
    __shared__ __align__(8) unsigned long long mb_empty[NSTAGE];

    const int t = threadIdx.x;
    const long long ntiles = NC / TILE;
    const long long rem = NC - ntiles * TILE;
    float* o0 = out;
    float* o1 = out + NC;
    float* o2 = out + 4 * NC;

    if (t == 0) {
        #pragma unroll
        for (int s = 0; s < NSTAGE; s++) {
            mbar_init(s2u(&mb_full[s]), 1);
            mbar_init(s2u(&mb_empty[s]), NCOMP);
        }
        asm volatile("fence.proxy.async.shared::cta;" ::: "memory");
    }
    __syncthreads();

    long long myN = 0;
    if ((long long)blockIdx.x < ntiles)
        myN = (ntiles - 1 - blockIdx.x) / gridDim.x + 1;

    if (t == NCOMP) {
        // ---------------- producer (single thread of warp 4) ----------------
        for (long long j = 0; j < myN; j++) {
            const int s = (int)(j % NSTAGE);
            const long long wrap = j / NSTAGE;
            if (wrap >= 1) mbar_wait(s2u(&mb_empty[s]), (int)((wrap - 1) & 1));
            const long long tile = blockIdx.x + j * (long long)gridDim.x;
            uint32_t mb = s2u(&mb_full[s]);
            mbar_expect_tx(mb, IN_BYTES);
            bulk_g2s(s2u(&sIn[s][0]),         x2 + tile * (TILE * 9), TILE * 36, mb);
            bulk_g2s(s2u(&sIn[s][TILE * 9]),  y2 + tile * (TILE * 9), TILE * 36, mb);
            bulk_g2s(s2u(&sIn[s][TILE * 18]), x1 + tile * (TILE * 3), TILE * 12, mb);
            bulk_g2s(s2u(&sIn[s][TILE * 21]), y1 + tile * (TILE * 3), TILE * 12, mb);
            bulk_g2s(s2u(&sIn[s][TILE * 24]), x0 + tile * TILE,       TILE * 4,  mb);
            bulk_g2s(s2u(&sIn[s][TILE * 25]), y0 + tile * TILE,       TILE * 4,  mb);
        }
    } else if (t < NCOMP) {
        // ---------------- compute + store (warps 0-3) ----------------
        for (long long k = 0; k < myN; k++) {
            const int s = (int)(k % NSTAGE);
            const long long wrap = k / NSTAGE;
            const long long tile = blockIdx.x + k * (long long)gridDim.x;

            mbar_wait(s2u(&mb_full[s]), (int)(wrap & 1));

            const float* in = sIn[s];
            float A[9], B[9], u[3], v[3];
            float a = in[TILE * 24 + t], b = in[TILE * 25 + t];
            #pragma unroll
            for (int i = 0; i < 9; i++) { A[i] = in[t * 9 + i]; B[i] = in[TILE * 9 + t * 9 + i]; }
            #pragma unroll
            for (int i = 0; i < 3; i++) { u[i] = in[TILE * 18 + t * 3 + i]; v[i] = in[TILE * 21 + t * 3 + i]; }

            // stage consumed -> let producer refill it while we compute/store
            mbar_arrive(s2u(&mb_empty[s]));

            float z0, z1[3], z2[9];
            tp_compute(a, b, u, v, A, B, z0, z1, z2);

            const int os = (int)(k & 1);
            // sOut[os] must be done being read by the store from iteration k-2
            if (t == 0) asm volatile("cp.async.bulk.wait_group.read 1;" ::: "memory");
            asm volatile("bar.sync 1, %0;" :: "n"(NCOMP) : "memory");

            float* po = sOut[os];
            #pragma unroll
            for (int i = 0; i < 9; i++) po[t * 9 + i] = z2[i];
            #pragma unroll
            for (int i = 0; i < 3; i++) po[TILE * 9 + t * 3 + i] = z1[i];
            po[TILE * 12 + t] = z0;

            asm volatile("bar.sync 1, %0;" :: "n"(NCOMP) : "memory");
            if (t == 0) {
                asm volatile("fence.proxy.async.shared::cta;" ::: "memory");
                bulk_s2g(o2 + tile * (TILE * 9), s2u(&sOut[os][0]),         TILE * 36);
                bulk_s2g(o1 + tile * (TILE * 3), s2u(&sOut[os][TILE * 9]),  TILE * 12);
                bulk_s2g(o0 + tile * TILE,       s2u(&sOut[os][TILE * 12]), TILE * 4);
                asm volatile("cp.async.bulk.commit_group;" ::: "memory");
            }
        }
        if (t == 0) asm volatile("cp.async.bulk.wait_group 0;" ::: "memory");

        // tail pairs (NC % TILE): block 0, direct global access
        if (blockIdx.x == 0 && rem > 0 && t < (int)rem) {
            long long p = ntiles * TILE + t;
            float a = x0[p], b = y0[p];
            float u[3], v[3], A[9], B[9];
            #pragma unroll
            for (int i = 0; i < 3; i++) { u[i] = x1[p * 3 + i]; v[i] = y1[p * 3 + i]; }
            #pragma unroll
            for (int i = 0; i < 9; i++) { A[i] = x2[p * 9 + i]; B[i] = y2[p * 9 + i]; }
            float z0, z1[3], z2[9];
            tp_compute(a, b, u, v, A, B, z0, z1, z2);
            o0[p] = z0;
            #pragma unroll
            for (int i = 0; i < 3; i++) o1[p * 3 + i] = z1[i];
            #pragma unroll
            for (int i = 0; i < 9; i++) o2[p * 9 + i] = z2[i];
        }
    }
}

// ---- fallback: one thread per pair, any alignment ----
__global__ void tp_simple(
    const float* __restrict__ x0, const float* __restrict__ y0,
    const float* __restrict__ x1, const float* __restrict__ y1,
    const float* __restrict__ x2, const float* __restrict__ y2,
    float* __restrict__ out, long long NC)
{
    long long p = (long long)blockIdx.x * blockDim.x + threadIdx.x;
    if (p >= NC) return;
    float a = x0[p], b = y0[p];
    float u[3], v[3], A[9], B[9];
    #pragma unroll
    for (int i = 0; i < 3; i++) { u[i] = x1[p * 3 + i]; v[i] = y1[p * 3 + i]; }
    #pragma unroll
    for (int i = 0; i < 9; i++) { A[i] = x2[p * 9 + i]; B[i] = y2[p * 9 + i]; }
    float z0, z1[3], z2[9];
    tp_compute(a, b, u, v, A, B, z0, z1, z2);
    out[p] = z0;
    #pragma unroll
    for (int i = 0; i < 3; i++) out[NC + p * 3 + i] = z1[i];
    #pragma unroll
    for (int i = 0; i < 9; i++) out[4 * NC + p * 9 + i] = z2[i];
}

extern "C" void kernel_launch(void* const* d_in, const int* in_sizes, int n_in,
                              void* d_out, int out_size)
{
    const long long NC = (long long)out_size / 13;

    const float *x0 = nullptr, *y0 = nullptr, *x1 = nullptr, *y1 = nullptr,
                *x2 = nullptr, *y2 = nullptr;
    for (int i = 0; i < n_in; i++) {
        long long s = in_sizes[i];
        const float* p = (const float*)d_in[i];
        if (s == NC)          { if (!x0) x0 = p; else y0 = p; }
        else if (s == 3 * NC) { if (!x1) x1 = p; else y1 = p; }
        else if (s == 9 * NC) { if (!x2) x2 = p; else y2 = p; }
    }

    auto a16 = [](const void* p) { return (((uintptr_t)p) & 15) == 0; };
    bool ok = (NC % 4 == 0) && a16(x0) && a16(y0) && a16(x1) && a16(y1) &&
              a16(x2) && a16(y2) && a16(d_out);

    if (ok) {
        long long ntiles = NC / TILE;
        int nblk = (int)(ntiles < 1 ? 1 : (ntiles < NBLK_MAX ? ntiles : NBLK_MAX));
        tp_ws<<<nblk, TPB>>>(x0, y0, x1, y1, x2, y2, (float*)d_out, NC);
    } else {
        int nblk = (int)((NC + 255) / 256);
        tp_simple<<<nblk, 256>>>(x0, y0, x1, y1, x2, y2, (float*)d_out, NC);
    }
}

// round 4
// speedup vs baseline: 1.0764x; 1.0764x over previous
#include <cuda_runtime.h>
#include <cstdint>

#define TPB 256

__device__ __forceinline__ float4 ldcs4(const float4* p) {
    return __ldcs(p);
}
__device__ __forceinline__ void stcs4(float4* p, float4 v) {
    __stcs(p, v);
}

__device__ __forceinline__ void tp_compute(
    float a, float b, const float* u, const float* v,
    const float* A, const float* B,
    float& z0, float* z1, float* z2)
{
    z0 = a * b;
    #pragma unroll
    for (int i = 0; i < 3; i++) z0 = fmaf(u[i], v[i], z0);
    #pragma unroll
    for (int i = 0; i < 9; i++) z0 = fmaf(A[i], B[i], z0);

    // z1_i = a*v_i + b*u_i + (u.B)_i + (A.v)_i
    #pragma unroll
    for (int i = 0; i < 3; i++) {
        float s = fmaf(a, v[i], b * u[i]);
        #pragma unroll
        for (int d = 0; d < 3; d++) {
            s = fmaf(u[d], B[d * 3 + i], s);
            s = fmaf(A[i * 3 + d], v[d], s);
        }
        z1[i] = s;
    }
    // z2_ij = a*B_ij + b*A_ij + u_i v_j + (A@B)_ij
    #pragma unroll
    for (int i = 0; i < 3; i++)
        #pragma unroll
        for (int j = 0; j < 3; j++) {
            float s = fmaf(a, B[i * 3 + j], b * A[i * 3 + j]);
            s = fmaf(u[i], v[j], s);
            #pragma unroll
            for (int k = 0; k < 3; k++)
                s = fmaf(A[i * 3 + k], B[k * 3 + j], s);
            z2[i * 3 + j] = s;
        }
}

__global__ __launch_bounds__(TPB) void tp_kernel(
    const float* __restrict__ x0, const float* __restrict__ y0,
    const float* __restrict__ x1, const float* __restrict__ y1,
    const float* __restrict__ x2, const float* __restrict__ y2,
    float* __restrict__ out, long long NC)
{
    __shared__ float sA[TPB * 9];
    __shared__ float sB[TPB * 9];
    __shared__ float su[TPB * 3];
    __shared__ float sv[TPB * 3];
    __shared__ float sa[TPB];
    __shared__ float sb[TPB];

    const long long base = (long long)blockIdx.x * TPB;
    const int t = threadIdx.x;
    long long rem = NC - base;
    const int npair = rem < TPB ? (int)rem : TPB;
    const bool full = (npair == TPB);

    // ---- Stage inputs into smem: coalesced float4 streaming loads ----
    if (full) {
        {
            const float4* gA = (const float4*)(x2 + base * 9);
            const float4* gB = (const float4*)(y2 + base * 9);
            float4* s4a = (float4*)sA;
            float4* s4b = (float4*)sB;
            #pragma unroll
            for (int i = t; i < TPB * 9 / 4; i += TPB) { s4a[i] = ldcs4(gA + i); s4b[i] = ldcs4(gB + i); }
        }
        {
            const float4* gu = (const float4*)(x1 + base * 3);
            const float4* gv = (const float4*)(y1 + base * 3);
            float4* s4u = (float4*)su;
            float4* s4v = (float4*)sv;
            #pragma unroll
            for (int i = t; i < TPB * 3 / 4; i += TPB) { s4u[i] = ldcs4(gu + i); s4v[i] = ldcs4(gv + i); }
        }
        {
            const float4* ga = (const float4*)(x0 + base);
            const float4* gb = (const float4*)(y0 + base);
            float4* s4a = (float4*)sa;
            float4* s4b = (float4*)sb;
            if (t < TPB / 4) { s4a[t] = ldcs4(ga + t); s4b[t] = ldcs4(gb + t); }
        }
    } else {
        for (int i = t; i < npair * 9; i += TPB) { sA[i] = x2[base * 9 + i]; sB[i] = y2[base * 9 + i]; }
        for (int i = t; i < npair * 3; i += TPB) { su[i] = x1[base * 3 + i]; sv[i] = y1[base * 3 + i]; }
        for (int i = t; i < npair;     i += TPB) { sa[i] = x0[base + i];     sb[i] = y0[base + i]; }
    }
    __syncthreads();

    // ---- Per-pair compute (smem strides 9/3/1 words: conflict-free) ----
    float z0 = 0.f, z1[3], z2[9];
    if (t < npair) {
        float a = sa[t], b = sb[t];
        float u[3], v[3], A[9], B[9];
        #pragma unroll
        for (int i = 0; i < 3; i++) { u[i] = su[t * 3 + i]; v[i] = sv[t * 3 + i]; }
        #pragma unroll
        for (int i = 0; i < 9; i++) { A[i] = sA[t * 9 + i]; B[i] = sB[t * 9 + i]; }
        tp_compute(a, b, u, v, A, B, z0, z1, z2);
    }
    __syncthreads();

    // ---- Stash results in smem (reuse buffers), then coalesced streaming stores ----
    if (t < npair) {
        sa[t] = z0;
        #pragma unroll
        for (int i = 0; i < 3; i++) su[t * 3 + i] = z1[i];
        #pragma unroll
        for (int i = 0; i < 9; i++) sA[t * 9 + i] = z2[i];
    }
    __syncthreads();

    float* o0 = out;
    float* o1 = out + NC;
    float* o2 = out + 4 * NC;
    if (full) {
        float4* g0 = (float4*)(o0 + base);
        float4* g1 = (float4*)(o1 + base * 3);
        float4* g2 = (float4*)(o2 + base * 9);
        const float4* s40 = (const float4*)sa;
        const float4* s41 = (const float4*)su;
        const float4* s42 = (const float4*)sA;
        if (t < TPB / 4) stcs4(g0 + t, s40[t]);
        #pragma unroll
        for (int i = t; i < TPB * 3 / 4; i += TPB) stcs4(g1 + i, s41[i]);
        #pragma unroll
        for (int i = t; i < TPB * 9 / 4; i += TPB) stcs4(g2 + i, s42[i]);
    } else {
        for (int i = t; i < npair;     i += TPB) o0[base + i]     = sa[i];
        for (int i = t; i < npair * 3; i += TPB) o1[base * 3 + i] = su[i];
        for (int i = t; i < npair * 9; i += TPB) o2[base * 9 + i] = sA[i];
    }
}

extern "C" void kernel_launch(void* const* d_in, const int* in_sizes, int n_in,
                              void* d_out, int out_size)
{
    // out = (z0, z1, z2) concatenated: 13*NC floats
    const long long NC = (long long)out_size / 13;

    // Classify inputs by element count; x precedes y within each size class
    // in both plausible metadata orderings.
    const float *x0 = nullptr, *y0 = nullptr, *x1 = nullptr, *y1 = nullptr,
                *x2 = nullptr, *y2 = nullptr;
    for (int i = 0; i < n_in; i++) {
        long long s = in_sizes[i];
        const float* p = (const float*)d_in[i];
        if (s == NC)          { if (!x0) x0 = p; else y0 = p; }
        else if (s == 3 * NC) { if (!x1) x1 = p; else y1 = p; }
        else if (s == 9 * NC) { if (!x2) x2 = p; else y2 = p; }
    }

    const int nblocks = (int)((NC + TPB - 1) / TPB);
    tp_kernel<<<nblocks, TPB>>>(x0, y0, x1, y1, x2, y2, (float*)d_out, NC);
}